// round 15
// baseline (speedup 1.0000x reference)
#include <cuda_runtime.h>

#define BB   4
#define HH   256
#define WW   256
#define CC   32
#define KF   5
#define NTAP 25

#define TW   16                 // tile width (px)
#define TH   8                  // tile height (2 rows/warp, 4 warps, 128 thr)
#define NTHR 128
#define TSW  36                 // floats per tap row in warp region (32 px + pad)
#define WREG (NTAP * TSW)       // 900 floats per warp
#define SMEM_BYTES (4 * WREG * 4)   // 14400 B

// single-row accum: 5 j-taps x 8 px x 2 ch, scalar FFMA
// tsp points at this row's pixel base inside the warp tap region.
__device__ __forceinline__ void accum(float* __restrict__ acc,
                                      const float* __restrict__ W,
                                      const float* __restrict__ tsp)
{
    #pragma unroll
    for (int j = 0; j < KF; j++) {
        const float4 tA = *(const float4*)(tsp + j * TSW);
        const float4 tB = *(const float4*)(tsp + j * TSW + 4);
        acc[ 0] += W[2*(0+j)  ] * tA.x;  acc[ 1] += W[2*(0+j)+1] * tA.x;
        acc[ 2] += W[2*(1+j)  ] * tA.y;  acc[ 3] += W[2*(1+j)+1] * tA.y;
        acc[ 4] += W[2*(2+j)  ] * tA.z;  acc[ 5] += W[2*(2+j)+1] * tA.z;
        acc[ 6] += W[2*(3+j)  ] * tA.w;  acc[ 7] += W[2*(3+j)+1] * tA.w;
        acc[ 8] += W[2*(4+j)  ] * tB.x;  acc[ 9] += W[2*(4+j)+1] * tB.x;
        acc[10] += W[2*(5+j)  ] * tB.y;  acc[11] += W[2*(5+j)+1] * tB.y;
        acc[12] += W[2*(6+j)  ] * tB.z;  acc[13] += W[2*(6+j)+1] * tB.z;
        acc[14] += W[2*(7+j)  ] * tB.w;  acc[15] += W[2*(7+j)+1] * tB.w;
    }
}

__global__ void __launch_bounds__(NTHR, 7)
kpc2d_kernel(const float* __restrict__ feat,
             const float* __restrict__ kern,
             const float* __restrict__ bias,
             float* __restrict__ out)
{
    extern __shared__ float ts[];   // [4 warps][NTAP][TSW]

    const int tid  = threadIdx.x;
    const int lane = tid & 31;
    const int wid  = tid >> 5;          // warp -> rows 2*wid, 2*wid+1
    const int cp   = lane & 15;         // channel pair: ch 2cp, 2cp+1
    const int half = lane >> 4;         // pixel half
    const int w0   = blockIdx.x * TW;
    const int h0   = blockIdx.y * TH;
    const int bz   = blockIdx.z;

    const int r0    = wid * 2;
    const int pbase = half * 8;
    float* wts = ts + wid * WREG;       // this warp's private tap region

    const bool interior = (h0 >= 2) && (h0 + TH + 2 <= HH) &&
                          (w0 >= 2) && (w0 + TW + 2 <= WW);
    const int fcol = ((bz * HH) * WW + (w0 + pbase - 2)) * CC + 2 * cp;

    // ---- hoist g=0 feat loads: latency hides behind the tap fill ----
    float W[24];
    if (interior) {
        const float* frow = feat + (fcol + (h0 + r0 - 2) * (WW * CC));
        #pragma unroll
        for (int c = 0; c < 12; c++) {
            const float2 f = __ldg((const float2*)(frow + c * CC));
            W[2*c] = f.x; W[2*c+1] = f.y;
        }
    }

    // ---- warp-private tap fill: 2 rows x 400 floats = 200 float4 ----
    // row0 taps -> cols 0..15, row1 taps -> cols 16..31 of [tap][TSW].
    {
        const float4* kern4 = (const float4*)kern;
        const unsigned kb = (unsigned)((bz * HH + h0 + r0) * WW + w0) * NTAP;
        #pragma unroll
        for (int it = 0; it < 7; it++) {
            const int chunk = lane + it * 32;
            if (chunk < 200) {
                const int row = (chunk >= 100) ? 1 : 0;
                const unsigned k4 = (unsigned)(chunk - row * 100) * 4u;
                const float4 v = __ldcs(kern4 +
                    ((kb + (unsigned)row * (WW * NTAP) + k4) >> 2));
                unsigned col = (k4 * 1311u) >> 15;       // k4/25 for k4<400
                unsigned tap = k4 - col * 25u;
                const unsigned roff = row * 16 + col;
                float vv[4] = {v.x, v.y, v.z, v.w};
                unsigned c2 = roff;
                #pragma unroll
                for (int e = 0; e < 4; e++) {
                    wts[tap * TSW + c2] = vv[e];
                    if (++tap == 25u) { tap = 0u; c2++; }
                }
            }
        }
    }

    const float2 bv = *(const float2*)(bias + 2 * cp);
    __syncwarp();

    // ---- compute: thread = 2 rows x 8 px x 2 ch, scalar FFMA ----
    float a0[16], a1[16];
    #pragma unroll
    for (int p = 0; p < 8; p++) {
        a0[2*p] = bv.x; a0[2*p+1] = bv.y;
        a1[2*p] = bv.x; a1[2*p+1] = bv.y;
    }

    const float* ts0 = wts + pbase;        // row-0 taps, this thread's px
    const float* ts1 = wts + 16 + pbase;   // row-1 taps

    if (interior) {
        // g = 0: W already loaded; only row-0 consumes it
        accum(a0, W, ts0);
        #pragma unroll
        for (int g = 1; g < 6; g++) {
            const float* frow = feat + (fcol + (h0 + r0 + g - 2) * (WW * CC));
            #pragma unroll
            for (int c = 0; c < 12; c++) {
                const float2 f = __ldg((const float2*)(frow + c * CC));
                W[2*c] = f.x; W[2*c+1] = f.y;
            }
            if (g < 5) accum(a0, W, ts0 + g * (KF * TSW));
            accum(a1, W, ts1 + (g - 1) * (KF * TSW));
        }
    } else {
        #pragma unroll 1
        for (int g = 0; g < 6; g++) {
            const int gh = h0 + r0 + g - 2;
            const bool rok = (unsigned)gh < HH;
            const float* frow = feat + (fcol + gh * (WW * CC));
            #pragma unroll
            for (int c = 0; c < 12; c++) {
                const int gw = w0 + pbase + c - 2;
                if (rok && (unsigned)gw < WW) {
                    const float2 f = __ldg((const float2*)(frow + c * CC));
                    W[2*c] = f.x; W[2*c+1] = f.y;
                } else {
                    W[2*c] = 0.f; W[2*c+1] = 0.f;
                }
            }
            if (g < 5) accum(a0, W, ts0 + (g    ) * (KF * TSW));
            if (g > 0) accum(a1, W, ts1 + (g - 1) * (KF * TSW));
        }
    }

    // ---- store: streaming, 2 rows x 8 px, STG.64 ----
    float* o0 = out + (((bz * HH + h0 + r0) * WW + (w0 + pbase)) * CC + 2 * cp);
    float* o1 = o0 + WW * CC;
    #pragma unroll
    for (int p = 0; p < 8; p++) {
        __stcs((float2*)(o0 + p * CC), make_float2(a0[2*p], a0[2*p+1]));
        __stcs((float2*)(o1 + p * CC), make_float2(a1[2*p], a1[2*p+1]));
    }
}

extern "C" void kernel_launch(void* const* d_in, const int* in_sizes, int n_in,
                              void* d_out, int out_size)
{
    const float* feat = (const float*)d_in[0];
    const float* kern = (const float*)d_in[1];
    const float* bias = (const float*)d_in[2];
    float* out = (float*)d_out;

    static bool attr_set = false;
    if (!attr_set) {
        cudaFuncSetAttribute(kpc2d_kernel,
                             cudaFuncAttributeMaxDynamicSharedMemorySize,
                             SMEM_BYTES);
        attr_set = true;
    }

    dim3 grid(WW / TW, HH / TH, BB);   // 16 x 32 x 4 = 2048 blocks
    kpc2d_kernel<<<grid, NTHR, SMEM_BYTES>>>(feat, kern, bias, out);
}

// round 16
// speedup vs baseline: 1.5632x; 1.5632x over previous
#include <cuda_runtime.h>

#define BB   4
#define HH   256
#define WW   256
#define CC   32
#define KF   5
#define NTAP 25

#define TW   16                 // tile width (px)
#define TH   8                  // tile height (2 rows/warp, 4 warps, 128 thr)
#define NTHR 128
#define TSS  132                // f32 stride per tap row (16B aligned, padded)
#define SMEM_BYTES (NTAP * TSS * 4)   // 13200 B

// one (feat-window, out-row): 5 j-taps x 8 px x 2 ch, scalar FFMA
__device__ __forceinline__ void accum(float* __restrict__ acc,
                                      const float* __restrict__ W,
                                      const float* __restrict__ tsp)
{
    #pragma unroll
    for (int j = 0; j < KF; j++) {
        const float4 tA = *(const float4*)(tsp + j * TSS);       // taps px0..3
        const float4 tB = *(const float4*)(tsp + j * TSS + 4);   // taps px4..7
        acc[ 0] += W[2*(0+j)  ] * tA.x;  acc[ 1] += W[2*(0+j)+1] * tA.x;
        acc[ 2] += W[2*(1+j)  ] * tA.y;  acc[ 3] += W[2*(1+j)+1] * tA.y;
        acc[ 4] += W[2*(2+j)  ] * tA.z;  acc[ 5] += W[2*(2+j)+1] * tA.z;
        acc[ 6] += W[2*(3+j)  ] * tA.w;  acc[ 7] += W[2*(3+j)+1] * tA.w;
        acc[ 8] += W[2*(4+j)  ] * tB.x;  acc[ 9] += W[2*(4+j)+1] * tB.x;
        acc[10] += W[2*(5+j)  ] * tB.y;  acc[11] += W[2*(5+j)+1] * tB.y;
        acc[12] += W[2*(6+j)  ] * tB.z;  acc[13] += W[2*(6+j)+1] * tB.z;
        acc[14] += W[2*(7+j)  ] * tB.w;  acc[15] += W[2*(7+j)+1] * tB.w;
    }
}

__global__ void __launch_bounds__(NTHR, 7)
kpc2d_kernel(const float* __restrict__ feat,
             const float* __restrict__ kern,
             const float* __restrict__ bias,
             float* __restrict__ out)
{
    extern __shared__ float ts[];   // [NTAP][TSS] scalar taps

    const int tid  = threadIdx.x;
    const int lane = tid & 31;
    const int wid  = tid >> 5;          // warp -> rows 2*wid, 2*wid+1
    const int cp   = lane & 15;         // channel pair: ch 2cp, 2cp+1
    const int half = lane >> 4;         // pixel half
    const int w0   = blockIdx.x * TW;
    const int h0   = blockIdx.y * TH;
    const int bz   = blockIdx.z;

    const int r0    = wid * 2;
    const int pbase = half * 8;
    const bool interior = (h0 >= 2) && (h0 + TH + 2 <= HH) &&
                          (w0 >= 2) && (w0 + TW + 2 <= WW);
    const int fcol = ((bz * HH) * WW + (w0 + pbase - 2)) * CC + 2 * cp;

    // ---- hoist g=0 feat loads: latency drains behind fill + barrier ----
    float W[24];
    if (interior) {
        const float* frow = feat + (fcol + (h0 + r0 - 2) * (WW * CC));
        #pragma unroll
        for (int c = 0; c < 12; c++) {
            const float2 f = __ldg((const float2*)(frow + c * CC));
            W[2*c] = f.x; W[2*c+1] = f.y;
        }
    }

    // ---- tap fill: streaming LDG.128 + magic divide + transposed STS ----
    const float4* kern4 = (const float4*)kern;
    const unsigned kbase = (unsigned)((bz * HH + h0) * WW + w0) * NTAP;
    #pragma unroll 1
    for (unsigned idx4 = tid; idx4 < TH * TW * NTAP / 4; idx4 += NTHR) {
        const unsigned row = idx4 / 100u;
        const unsigned k4  = (idx4 - row * 100u) * 4u;   // 0..396
        const unsigned fidx = kbase + row * (unsigned)(WW * NTAP) + k4;
        const float4 v = __ldcs(kern4 + (fidx >> 2));    // read-once
        unsigned col = (k4 * 1311u) >> 15;               // k4/25 for k4<400
        unsigned tap = k4 - col * 25u;
        const unsigned pb = row * TW;
        float vv[4] = {v.x, v.y, v.z, v.w};
        #pragma unroll
        for (int e = 0; e < 4; e++) {
            ts[tap * TSS + pb + col] = vv[e];
            if (++tap == 25u) { tap = 0u; col++; }
        }
    }

    const float2 bv = *(const float2*)(bias + 2 * cp);
    __syncthreads();

    // ---- compute: thread = 2 rows x 8 px x 2 ch, scalar FFMA ----
    float a0[16], a1[16];
    #pragma unroll
    for (int p = 0; p < 8; p++) {
        a0[2*p] = bv.x; a0[2*p+1] = bv.y;
        a1[2*p] = bv.x; a1[2*p+1] = bv.y;
    }

    const float* ts0 = ts + r0 * TW + pbase;   // row-0 tap pixel base
    const float* ts1 = ts0 + TW;               // row-1 tap pixel base

    if (interior) {
        // g = 0: W already loaded above the barrier; only row-0 consumes it
        accum(a0, W, ts0);
        #pragma unroll
        for (int g = 1; g < 6; g++) {
            const int gh = h0 + r0 + g - 2;
            const float* frow = feat + (fcol + gh * (WW * CC));
            #pragma unroll
            for (int c = 0; c < 12; c++) {
                const float2 f = __ldg((const float2*)(frow + c * CC));
                W[2*c] = f.x; W[2*c+1] = f.y;
            }
            if (g < 5) accum(a0, W, ts0 + (g    ) * (KF * TSS));
            accum(a1, W, ts1 + (g - 1) * (KF * TSS));
        }
    } else {
        #pragma unroll 1
        for (int g = 0; g < 6; g++) {
            const int gh = h0 + r0 + g - 2;
            const bool rok = (unsigned)gh < HH;
            const float* frow = feat + (fcol + gh * (WW * CC));
            #pragma unroll
            for (int c = 0; c < 12; c++) {
                const int gw = w0 + pbase + c - 2;
                if (rok && (unsigned)gw < WW) {
                    const float2 f = __ldg((const float2*)(frow + c * CC));
                    W[2*c] = f.x; W[2*c+1] = f.y;
                } else {
                    W[2*c] = 0.f; W[2*c+1] = 0.f;
                }
            }
            if (g < 5) accum(a0, W, ts0 + (g    ) * (KF * TSS));
            if (g > 0) accum(a1, W, ts1 + (g - 1) * (KF * TSS));
        }
    }

    // ---- store: streaming, 2 rows x 8 px, STG.64 ----
    float* o0 = out + (((bz * HH + h0 + r0) * WW + (w0 + pbase)) * CC + 2 * cp);
    float* o1 = o0 + WW * CC;
    #pragma unroll
    for (int p = 0; p < 8; p++) {
        __stcs((float2*)(o0 + p * CC), make_float2(a0[2*p], a0[2*p+1]));
        __stcs((float2*)(o1 + p * CC), make_float2(a1[2*p], a1[2*p+1]));
    }
}

extern "C" void kernel_launch(void* const* d_in, const int* in_sizes, int n_in,
                              void* d_out, int out_size)
{
    const float* feat = (const float*)d_in[0];
    const float* kern = (const float*)d_in[1];
    const float* bias = (const float*)d_in[2];
    float* out = (float*)d_out;

    static bool attr_set = false;
    if (!attr_set) {
        cudaFuncSetAttribute(kpc2d_kernel,
                             cudaFuncAttributeMaxDynamicSharedMemorySize,
                             SMEM_BYTES);
        attr_set = true;
    }

    dim3 grid(WW / TW, HH / TH, BB);   // 16 x 32 x 4 = 2048 blocks
    kpc2d_kernel<<<grid, NTHR, SMEM_BYTES>>>(feat, kern, bias, out);
}